// round 6
// baseline (speedup 1.0000x reference)
#include <cuda_runtime.h>
#include <cuda_bf16.h>

// Blur (upfirdn2d, 4x4 FIR = outer([1,3,3,1])/16, pad=(2,1), stride 1)
// x: (B,C,256,256) fp32 -> y: same shape.
// y[p][q] = sum_{a,b} K[a][b] * x[p+1-a][q+1-b]  (zero padded)
//
// R6: R4's burst structure (front-batched 8 LDG per 4-row block, 3 CTAs/SM)
// + register-free pipeline depth via prefetch.global.L2 issued two blocks
// ahead (demand loads then hit L2 at ~240cyc instead of DRAM ~577cyc).
// 16 rows/thread to amortize halo prologue. Shuffle horizontal halo,
// separable immediate-FMA FIR.

#define HH 256
#define WW 256
#define TILE_ROWS 128
#define ROWS_PER_THREAD 16

// Load one row segment (two aligned float4), zero-filled out of range.
// r must be warp-uniform.
__device__ __forceinline__ void ldrow(const float* __restrict__ xin,
                                      int r, int q0, float4& a, float4& b) {
    if (r >= 0 && r < HH) {
        const float4* p = reinterpret_cast<const float4*>(xin + r * WW + q0);
        a = p[0];
        b = p[1];
    } else {
        a = make_float4(0.f, 0.f, 0.f, 0.f);
        b = a;
    }
}

// Prefetch one input row into L2. Lanes 0,4,...,28 each cover one distinct
// 128B line -> whole 1KB row, one warp-instruction, no registers written.
__device__ __forceinline__ void pfrow(const float* __restrict__ xin,
                                      int r, int q0, int lane) {
    if (r >= 0 && r < HH && (lane & 3) == 0) {
        const float* p = xin + r * WW + q0;
        asm volatile("prefetch.global.L2 [%0];" :: "l"(p));
    }
}

// Horizontal FIR on a staged row: h[i] = (x[q+1]+3x[q]+3x[q-1]+x[q-2])/16.
// Halo via warp shuffle (warp spans the full 256-col row; lane 0/31 edges
// are exactly the conv zero-padding). Warp-collective.
__device__ __forceinline__ void hmath(float4 a, float4 b, int lane,
                                      float* __restrict__ h) {
    float lm2 = __shfl_up_sync(0xFFFFFFFFu, b.z, 1);
    float lm1 = __shfl_up_sync(0xFFFFFFFFu, b.w, 1);
    float rp1 = __shfl_down_sync(0xFFFFFFFFu, a.x, 1);
    if (lane == 0)  { lm2 = 0.0f; lm1 = 0.0f; }
    if (lane == 31) { rp1 = 0.0f; }

    float v[11];
    v[0] = lm2; v[1] = lm1;
    v[2] = a.x; v[3] = a.y; v[4] = a.z; v[5] = a.w;
    v[6] = b.x; v[7] = b.y; v[8] = b.z; v[9] = b.w;
    v[10] = rp1;

    #pragma unroll
    for (int i = 0; i < 8; i++) {
        float t = fmaf(v[i + 2], 3.0f, v[i + 3]);
        t = fmaf(v[i + 1], 3.0f, t);
        t = t + v[i];
        h[i] = t * 0.0625f;
    }
}

// y = hD + 3*hC + 3*hB + hA  (hD newest = h(p+1), hA oldest = h(p-2))
__device__ __forceinline__ void emit_row(const float* __restrict__ hA,
                                         const float* __restrict__ hB,
                                         const float* __restrict__ hC,
                                         const float* __restrict__ hD,
                                         float* __restrict__ outp) {
    float y[8];
    #pragma unroll
    for (int i = 0; i < 8; i++) {
        float u = fmaf(hC[i], 3.0f, hD[i]);
        u = fmaf(hB[i], 3.0f, u);
        y[i] = u + hA[i];
    }
    *reinterpret_cast<float4*>(outp)     = make_float4(y[0], y[1], y[2], y[3]);
    *reinterpret_cast<float4*>(outp + 4) = make_float4(y[4], y[5], y[6], y[7]);
}

__global__ __launch_bounds__(256, 3)
void Blur_455266533538_kernel(const float* __restrict__ x,
                              const float* __restrict__ kern,
                              float* __restrict__ out, int nimg) {
    int tile = blockIdx.x & 1;            // 2 tiles of 128 rows per image
    int img  = blockIdx.x >> 1;
    if (img >= nimg) return;

    int tid   = threadIdx.x;
    int lane  = tid & 31;
    int chunk = tid >> 5;
    int q0 = lane * 8;
    int r0 = tile * TILE_ROWS + chunk * ROWS_PER_THREAD;

    const float* xin = x   + (size_t)img * (HH * WW);
    float*       yo  = out + (size_t)img * (HH * WW);

    // Verify kernel == outer([1,3,3,1])/16 (exact in fp32).
    bool fast = true;
    float wva[4] = {1.0f, 3.0f, 3.0f, 1.0f};
    #pragma unroll
    for (int a = 0; a < 4; a++) {
        #pragma unroll
        for (int b = 0; b < 4; b++) {
            float expect = wva[a] * wva[b] * 0.0625f;
            if (fabsf(__ldg(&kern[a * 4 + b]) - expect) > 1e-7f) fast = false;
        }
    }

    if (fast) {
        float h0[8], h1[8], h2[8], h3[8];
        float4 a0, b0, a1, b1, a2, b2, a3, b3;

        // Prologue: batch-load 3 halo rows; prefetch block 1 (rows r0+5..r0+8).
        ldrow(xin, r0 - 2, q0, a0, b0);
        ldrow(xin, r0 - 1, q0, a1, b1);
        ldrow(xin, r0,     q0, a2, b2);
        pfrow(xin, r0 + 5, q0, lane);
        pfrow(xin, r0 + 6, q0, lane);
        pfrow(xin, r0 + 7, q0, lane);
        pfrow(xin, r0 + 8, q0, lane);
        hmath(a0, b0, lane, h0);
        hmath(a1, b1, lane, h1);
        hmath(a2, b2, lane, h2);

        #pragma unroll 1
        for (int pp = 0; pp < ROWS_PER_THREAD; pp += 4) {
            int p = r0 + pp;
            // Demand loads for this block (8 x LDG.128, back-to-back).
            ldrow(xin, p + 1, q0, a0, b0);
            ldrow(xin, p + 2, q0, a1, b1);
            ldrow(xin, p + 3, q0, a2, b2);
            ldrow(xin, p + 4, q0, a3, b3);
            // Prefetch the block TWO ahead (rows p+9..p+12) into L2.
            pfrow(xin, p + 9,  q0, lane);
            pfrow(xin, p + 10, q0, lane);
            pfrow(xin, p + 11, q0, lane);
            pfrow(xin, p + 12, q0, lane);
            // Consume in arrival order.
            hmath(a0, b0, lane, h3);
            emit_row(h0, h1, h2, h3, yo + (p + 0) * WW + q0);
            hmath(a1, b1, lane, h0);
            emit_row(h1, h2, h3, h0, yo + (p + 1) * WW + q0);
            hmath(a2, b2, lane, h1);
            emit_row(h2, h3, h0, h1, yo + (p + 2) * WW + q0);
            hmath(a3, b3, lane, h2);
            emit_row(h3, h0, h1, h2, yo + (p + 3) * WW + q0);
        }
    } else {
        // Exact general fallback: direct 16-tap convolution.
        float kk[16];
        #pragma unroll
        for (int i = 0; i < 16; i++) kk[i] = __ldg(&kern[i]);

        for (int pr = 0; pr < ROWS_PER_THREAD; pr++) {
            int p = r0 + pr;
            for (int qc = 0; qc < 8; qc++) {
                int q = q0 + qc;
                float acc = 0.0f;
                #pragma unroll
                for (int a = 0; a < 4; a++) {
                    int rr = p + 1 - a;
                    if (rr < 0 || rr >= HH) continue;
                    #pragma unroll
                    for (int b = 0; b < 4; b++) {
                        int cc = q + 1 - b;
                        if (cc < 0 || cc >= WW) continue;
                        acc = fmaf(kk[a * 4 + b], xin[rr * WW + cc], acc);
                    }
                }
                yo[p * WW + q] = acc;
            }
        }
    }
}

extern "C" void kernel_launch(void* const* d_in, const int* in_sizes, int n_in,
                              void* d_out, int out_size) {
    const float* x    = (const float*)d_in[0];
    const float* kern = (const float*)d_in[1];
    float* out = (float*)d_out;

    int n = in_sizes[0];
    int nimg = n / (HH * WW);   // B*C images of 256x256

    Blur_455266533538_kernel<<<nimg * 2, 256>>>(x, kern, out, nimg);
}

// round 7
// speedup vs baseline: 1.2195x; 1.2195x over previous
#include <cuda_runtime.h>
#include <cuda_bf16.h>

// Blur (upfirdn2d, 4x4 FIR = outer([1,3,3,1])/16, pad=(2,1), stride 1)
// x: (B,C,256,256) fp32 -> y: same shape.
// y[p][q] = sum_{a,b} K[a][b] * x[p+1-a][q+1-b]  (zero padded)
//
// R7: contiguous dual-segment ownership. Lane i owns cols [4i,4i+4) and
// [128+4i,128+4i+4), so every LDG.128/STG.128 is a contiguous 512B warp
// access (4 L1tex wavefronts instead of 8 for the old 32B-strided layout).
// Halo via warp shuffles incl. the col-127/128 seam stitched in-warp.
// R4 burst pipeline: 8 LDG front-batched per 4-row block, 3 CTAs/SM.

#define HH 256
#define WW 256
#define TILE_ROWS 64
#define ROWS_PER_THREAD 8

// Load one row (two contiguous-512B LDG.128), zero-filled out of range.
// r must be warp-uniform.
__device__ __forceinline__ void ldrow(const float* __restrict__ xin,
                                      int r, int lane, float4& A, float4& B) {
    if (r >= 0 && r < HH) {
        const float* rowp = xin + r * WW + 4 * lane;
        A = *reinterpret_cast<const float4*>(rowp);         // cols 4i..4i+3
        B = *reinterpret_cast<const float4*>(rowp + 128);   // cols 128+4i..
    } else {
        A = make_float4(0.f, 0.f, 0.f, 0.f);
        B = A;
    }
}

// Horizontal FIR: h[j] = (x[q+1]+3x[q]+3x[q-1]+x[q-2])/16.
// h[0..3] -> cols 4i+j ; h[4..7] -> cols 128+4i+j.
// Halo via warp shuffle; the col-127/128 seam is stitched across lanes
// 31<->0 inside the warp; image edges are the conv zero-padding.
// Warp-collective (r uniform per warp).
__device__ __forceinline__ void hmath(float4 A, float4 Bv, int lane,
                                      float* __restrict__ h) {
    const unsigned m = 0xFFFFFFFFu;
    float Az_up = __shfl_up_sync(m, A.z, 1);
    float Aw_up = __shfl_up_sync(m, A.w, 1);
    float Ax_dn = __shfl_down_sync(m, A.x, 1);
    float Bz_up = __shfl_up_sync(m, Bv.z, 1);
    float Bw_up = __shfl_up_sync(m, Bv.w, 1);
    float Bx_dn = __shfl_down_sync(m, Bv.x, 1);
    float Az31  = __shfl_sync(m, A.z, 31);    // col 126
    float Aw31  = __shfl_sync(m, A.w, 31);    // col 127
    float Bx0   = __shfl_sync(m, Bv.x, 0);    // col 128

    float vA[7], vB[7];
    vA[0] = (lane == 0)  ? 0.0f : Az_up;      // col 4i-2
    vA[1] = (lane == 0)  ? 0.0f : Aw_up;      // col 4i-1
    vA[2] = A.x; vA[3] = A.y; vA[4] = A.z; vA[5] = A.w;
    vA[6] = (lane == 31) ? Bx0  : Ax_dn;      // col 4i+4 (seam at lane 31)

    vB[0] = (lane == 0)  ? Az31 : Bz_up;      // col 128+4i-2 (seam at lane 0)
    vB[1] = (lane == 0)  ? Aw31 : Bw_up;      // col 128+4i-1
    vB[2] = Bv.x; vB[3] = Bv.y; vB[4] = Bv.z; vB[5] = Bv.w;
    vB[6] = (lane == 31) ? 0.0f : Bx_dn;      // col 128+4i+4 (right edge)

    #pragma unroll
    for (int j = 0; j < 4; j++) {
        float t = fmaf(vA[j + 2], 3.0f, vA[j + 3]);
        t = fmaf(vA[j + 1], 3.0f, t);
        t = t + vA[j];
        h[j] = t * 0.0625f;
    }
    #pragma unroll
    for (int j = 0; j < 4; j++) {
        float t = fmaf(vB[j + 2], 3.0f, vB[j + 3]);
        t = fmaf(vB[j + 1], 3.0f, t);
        t = t + vB[j];
        h[4 + j] = t * 0.0625f;
    }
}

// y = hD + 3*hC + 3*hB + hA; two contiguous-512B STG.128.
__device__ __forceinline__ void emit_row(const float* __restrict__ hA,
                                         const float* __restrict__ hB,
                                         const float* __restrict__ hC,
                                         const float* __restrict__ hD,
                                         float* __restrict__ yrow, int lane) {
    float y[8];
    #pragma unroll
    for (int i = 0; i < 8; i++) {
        float u = fmaf(hC[i], 3.0f, hD[i]);
        u = fmaf(hB[i], 3.0f, u);
        y[i] = u + hA[i];
    }
    float* p = yrow + 4 * lane;
    *reinterpret_cast<float4*>(p)       = make_float4(y[0], y[1], y[2], y[3]);
    *reinterpret_cast<float4*>(p + 128) = make_float4(y[4], y[5], y[6], y[7]);
}

__global__ __launch_bounds__(256, 3)
void Blur_455266533538_kernel(const float* __restrict__ x,
                              const float* __restrict__ kern,
                              float* __restrict__ out, int nimg) {
    int tile = blockIdx.x & 3;            // 4 tiles of 64 rows per image
    int img  = blockIdx.x >> 2;
    if (img >= nimg) return;

    int tid   = threadIdx.x;
    int lane  = tid & 31;
    int chunk = tid >> 5;
    int r0 = tile * TILE_ROWS + chunk * ROWS_PER_THREAD;

    const float* xin = x   + (size_t)img * (HH * WW);
    float*       yo  = out + (size_t)img * (HH * WW);

    // Verify kernel == outer([1,3,3,1])/16 (exact in fp32).
    bool fast = true;
    float wva[4] = {1.0f, 3.0f, 3.0f, 1.0f};
    #pragma unroll
    for (int a = 0; a < 4; a++) {
        #pragma unroll
        for (int b = 0; b < 4; b++) {
            float expect = wva[a] * wva[b] * 0.0625f;
            if (fabsf(__ldg(&kern[a * 4 + b]) - expect) > 1e-7f) fast = false;
        }
    }

    if (fast) {
        float h0[8], h1[8], h2[8], h3[8];
        float4 a0, b0, a1, b1, a2, b2, a3, b3;

        // Prologue: batch-load 3 halo rows, then filter them.
        ldrow(xin, r0 - 2, lane, a0, b0);
        ldrow(xin, r0 - 1, lane, a1, b1);
        ldrow(xin, r0,     lane, a2, b2);
        hmath(a0, b0, lane, h0);
        hmath(a1, b1, lane, h1);
        hmath(a2, b2, lane, h2);

        #pragma unroll 1
        for (int pp = 0; pp < ROWS_PER_THREAD; pp += 4) {
            int p = r0 + pp;
            // Front-batch ALL loads for this block (8 x LDG.128).
            ldrow(xin, p + 1, lane, a0, b0);
            ldrow(xin, p + 2, lane, a1, b1);
            ldrow(xin, p + 3, lane, a2, b2);
            ldrow(xin, p + 4, lane, a3, b3);
            // Consume in arrival order.
            hmath(a0, b0, lane, h3);
            emit_row(h0, h1, h2, h3, yo + (p + 0) * WW, lane);
            hmath(a1, b1, lane, h0);
            emit_row(h1, h2, h3, h0, yo + (p + 1) * WW, lane);
            hmath(a2, b2, lane, h1);
            emit_row(h2, h3, h0, h1, yo + (p + 2) * WW, lane);
            hmath(a3, b3, lane, h2);
            emit_row(h3, h0, h1, h2, yo + (p + 3) * WW, lane);
        }
    } else {
        // Exact general fallback: direct 16-tap convolution over this
        // thread's two 4-col segments.
        float kk[16];
        #pragma unroll
        for (int i = 0; i < 16; i++) kk[i] = __ldg(&kern[i]);

        for (int pr = 0; pr < ROWS_PER_THREAD; pr++) {
            int p = r0 + pr;
            for (int qc = 0; qc < 8; qc++) {
                int q = (qc < 4) ? (4 * lane + qc) : (128 + 4 * lane + qc - 4);
                float acc = 0.0f;
                #pragma unroll
                for (int a = 0; a < 4; a++) {
                    int rr = p + 1 - a;
                    if (rr < 0 || rr >= HH) continue;
                    #pragma unroll
                    for (int b = 0; b < 4; b++) {
                        int cc = q + 1 - b;
                        if (cc < 0 || cc >= WW) continue;
                        acc = fmaf(kk[a * 4 + b], xin[rr * WW + cc], acc);
                    }
                }
                yo[p * WW + q] = acc;
            }
        }
    }
}

extern "C" void kernel_launch(void* const* d_in, const int* in_sizes, int n_in,
                              void* d_out, int out_size) {
    const float* x    = (const float*)d_in[0];
    const float* kern = (const float*)d_in[1];
    float* out = (float*)d_out;

    int n = in_sizes[0];
    int nimg = n / (HH * WW);   // B*C images of 256x256

    Blur_455266533538_kernel<<<nimg * 4, 256>>>(x, kern, out, nimg);
}

// round 8
// speedup vs baseline: 1.2365x; 1.0140x over previous
#include <cuda_runtime.h>
#include <cuda_bf16.h>

// Blur (upfirdn2d, 4x4 FIR = outer([1,3,3,1])/16, pad=(2,1), stride 1)
// x: (B,C,256,256) fp32 -> y: same shape.
// y[p][q] = sum_{a,b} K[a][b] * x[p+1-a][q+1-b]  (zero padded)
//
// R8: cp.async (LDGSTS) software pipeline. Loads go global->smem via
// cp.async.cg (zero registers, L1 bypass, commit/wait-group tracking),
// keeping 2 stages (4KB) per warp in flight CONTINUOUSLY at 3 CTAs/SM —
// sustained MLP + occupancy together for the first time. Per-warp ring of
// 3 smem slots x 2 rows (8 warps x 6KB = 48KB static). Consume uses R7's
// contiguous dual-segment layout (LDS.128) + shuffle halo + separable
// immediate-FMA FIR. OOB rows zero-filled via cp.async src-size=0.

#define HH 256
#define WW 256
#define TILE_ROWS 64
#define ROWS_PER_THREAD 8

// ---- cp.async helpers ----
__device__ __forceinline__ void cp16(float* dst, const float* src, int valid) {
    unsigned d = (unsigned)__cvta_generic_to_shared(dst);
    int sz = valid ? 16 : 0;   // src-size=0 -> 16B of zeros (conv zero-pad)
    asm volatile("cp.async.cg.shared.global [%0], [%1], 16, %2;"
                 :: "r"(d), "l"(src), "r"(sz));
}

// Issue one stage = rows (r, r+1) of the image into a 2-row smem slot.
// Lane i covers cols [4i,4i+4) and [128+4i,128+4i+4) of each row.
__device__ __forceinline__ void issue_stage(float* slotbase,
                                            const float* __restrict__ xin,
                                            int r, int lane) {
    #pragma unroll
    for (int k = 0; k < 2; k++) {
        int row = r + k;
        int valid = (row >= 0 && row < HH) ? 1 : 0;
        const float* src = xin + (size_t)(valid ? row : 0) * WW + 4 * lane;
        cp16(slotbase + k * 256 + 4 * lane,       src,       valid);
        cp16(slotbase + k * 256 + 128 + 4 * lane, src + 128, valid);
    }
    asm volatile("cp.async.commit_group;");
}

template <int N>
__device__ __forceinline__ void wait_stages() {
    asm volatile("cp.async.wait_group %0;" :: "n"(N));
    __syncwarp();
}

__device__ __forceinline__ void lds_row(const float* rowbase, int lane,
                                        float4& A, float4& B) {
    A = *reinterpret_cast<const float4*>(rowbase + 4 * lane);
    B = *reinterpret_cast<const float4*>(rowbase + 128 + 4 * lane);
}

// Horizontal FIR: h[j] = (x[q+1]+3x[q]+3x[q-1]+x[q-2])/16.
// h[0..3] -> cols 4i+j ; h[4..7] -> cols 128+4i+j. Halo via warp shuffle;
// col-127/128 seam stitched across lanes 31<->0; image edges = zero pad.
__device__ __forceinline__ void hmath(float4 A, float4 Bv, int lane,
                                      float* __restrict__ h) {
    const unsigned m = 0xFFFFFFFFu;
    float Az_up = __shfl_up_sync(m, A.z, 1);
    float Aw_up = __shfl_up_sync(m, A.w, 1);
    float Ax_dn = __shfl_down_sync(m, A.x, 1);
    float Bz_up = __shfl_up_sync(m, Bv.z, 1);
    float Bw_up = __shfl_up_sync(m, Bv.w, 1);
    float Bx_dn = __shfl_down_sync(m, Bv.x, 1);
    float Az31  = __shfl_sync(m, A.z, 31);    // col 126
    float Aw31  = __shfl_sync(m, A.w, 31);    // col 127
    float Bx0   = __shfl_sync(m, Bv.x, 0);    // col 128

    float vA[7], vB[7];
    vA[0] = (lane == 0)  ? 0.0f : Az_up;
    vA[1] = (lane == 0)  ? 0.0f : Aw_up;
    vA[2] = A.x; vA[3] = A.y; vA[4] = A.z; vA[5] = A.w;
    vA[6] = (lane == 31) ? Bx0  : Ax_dn;

    vB[0] = (lane == 0)  ? Az31 : Bz_up;
    vB[1] = (lane == 0)  ? Aw31 : Bw_up;
    vB[2] = Bv.x; vB[3] = Bv.y; vB[4] = Bv.z; vB[5] = Bv.w;
    vB[6] = (lane == 31) ? 0.0f : Bx_dn;

    #pragma unroll
    for (int j = 0; j < 4; j++) {
        float t = fmaf(vA[j + 2], 3.0f, vA[j + 3]);
        t = fmaf(vA[j + 1], 3.0f, t);
        t = t + vA[j];
        h[j] = t * 0.0625f;
    }
    #pragma unroll
    for (int j = 0; j < 4; j++) {
        float t = fmaf(vB[j + 2], 3.0f, vB[j + 3]);
        t = fmaf(vB[j + 1], 3.0f, t);
        t = t + vB[j];
        h[4 + j] = t * 0.0625f;
    }
}

// y = hD + 3*hC + 3*hB + hA; two contiguous-512B STG.128.
__device__ __forceinline__ void emit_row(const float* __restrict__ hA,
                                         const float* __restrict__ hB,
                                         const float* __restrict__ hC,
                                         const float* __restrict__ hD,
                                         float* __restrict__ yrow, int lane) {
    float y[8];
    #pragma unroll
    for (int i = 0; i < 8; i++) {
        float u = fmaf(hC[i], 3.0f, hD[i]);
        u = fmaf(hB[i], 3.0f, u);
        y[i] = u + hA[i];
    }
    float* p = yrow + 4 * lane;
    *reinterpret_cast<float4*>(p)       = make_float4(y[0], y[1], y[2], y[3]);
    *reinterpret_cast<float4*>(p + 128) = make_float4(y[4], y[5], y[6], y[7]);
}

__global__ __launch_bounds__(256, 3)
void Blur_455266533538_kernel(const float* __restrict__ x,
                              const float* __restrict__ kern,
                              float* __restrict__ out, int nimg) {
    // [warp][slot][2 rows * 256 floats] = 8*3*512*4B = 48KB
    __shared__ float smbuf[8][3][512];

    int tile = blockIdx.x & 3;            // 4 tiles of 64 rows per image
    int img  = blockIdx.x >> 2;
    if (img >= nimg) return;

    int tid  = threadIdx.x;
    int lane = tid & 31;
    int warp = tid >> 5;
    int r0 = tile * TILE_ROWS + warp * ROWS_PER_THREAD;

    const float* xin = x   + (size_t)img * (HH * WW);
    float*       yo  = out + (size_t)img * (HH * WW);

    // Verify kernel == outer([1,3,3,1])/16 (exact in fp32).
    bool fast = true;
    float wva[4] = {1.0f, 3.0f, 3.0f, 1.0f};
    #pragma unroll
    for (int a = 0; a < 4; a++) {
        #pragma unroll
        for (int b = 0; b < 4; b++) {
            float expect = wva[a] * wva[b] * 0.0625f;
            if (fabsf(__ldg(&kern[a * 4 + b]) - expect) > 1e-7f) fast = false;
        }
    }

    if (fast) {
        float* s0 = &smbuf[warp][0][0];
        float* s1 = &smbuf[warp][1][0];
        float* s2 = &smbuf[warp][2][0];

        // Fill the ring: stages cover input rows r0-2..r0+3.
        issue_stage(s0, xin, r0 - 2, lane);   // rows r0-2, r0-1
        issue_stage(s1, xin, r0,     lane);   // rows r0,   r0+1
        issue_stage(s2, xin, r0 + 2, lane);   // rows r0+2, r0+3

        float h0[8], h1[8], h2[8], h3[8];
        float4 A, B, A2, B2;

        wait_stages<2>();                     // s0 ready
        lds_row(s0,       lane, A,  B);
        lds_row(s0 + 256, lane, A2, B2);
        hmath(A,  B,  lane, h0);              // h(r0-2)
        hmath(A2, B2, lane, h1);              // h(r0-1)
        issue_stage(s0, xin, r0 + 4, lane);   // rows r0+4, r0+5

        wait_stages<2>();                     // s1 ready
        lds_row(s1,       lane, A,  B);
        lds_row(s1 + 256, lane, A2, B2);
        hmath(A,  B,  lane, h2);              // h(r0)
        hmath(A2, B2, lane, h3);              // h(r0+1)
        emit_row(h0, h1, h2, h3, yo + (r0 + 0) * WW, lane);
        issue_stage(s1, xin, r0 + 6, lane);   // rows r0+6, r0+7

        wait_stages<2>();                     // s2 ready (r0+2, r0+3)
        lds_row(s2,       lane, A,  B);
        lds_row(s2 + 256, lane, A2, B2);
        hmath(A,  B,  lane, h0);              // h(r0+2)
        emit_row(h1, h2, h3, h0, yo + (r0 + 1) * WW, lane);
        hmath(A2, B2, lane, h1);              // h(r0+3)
        emit_row(h2, h3, h0, h1, yo + (r0 + 2) * WW, lane);
        issue_stage(s2, xin, r0 + 8, lane);   // rows r0+8 (r0+9 OOB/unused)

        wait_stages<2>();                     // s3 ready (r0+4, r0+5) in s0
        lds_row(s0,       lane, A,  B);
        lds_row(s0 + 256, lane, A2, B2);
        hmath(A,  B,  lane, h2);              // h(r0+4)
        emit_row(h3, h0, h1, h2, yo + (r0 + 3) * WW, lane);
        hmath(A2, B2, lane, h3);              // h(r0+5)
        emit_row(h0, h1, h2, h3, yo + (r0 + 4) * WW, lane);

        wait_stages<1>();                     // s4 ready (r0+6, r0+7) in s1
        lds_row(s1,       lane, A,  B);
        lds_row(s1 + 256, lane, A2, B2);
        hmath(A,  B,  lane, h0);              // h(r0+6)
        emit_row(h1, h2, h3, h0, yo + (r0 + 5) * WW, lane);
        hmath(A2, B2, lane, h1);              // h(r0+7)
        emit_row(h2, h3, h0, h1, yo + (r0 + 6) * WW, lane);

        wait_stages<0>();                     // s5 ready (r0+8) in s2
        lds_row(s2, lane, A, B);
        hmath(A, B, lane, h2);                // h(r0+8)
        emit_row(h3, h0, h1, h2, yo + (r0 + 7) * WW, lane);
    } else {
        // Exact general fallback: direct 16-tap convolution over this
        // thread's two 4-col segments.
        float kk[16];
        #pragma unroll
        for (int i = 0; i < 16; i++) kk[i] = __ldg(&kern[i]);

        for (int pr = 0; pr < ROWS_PER_THREAD; pr++) {
            int p = r0 + pr;
            for (int qc = 0; qc < 8; qc++) {
                int q = (qc < 4) ? (4 * lane + qc) : (128 + 4 * lane + qc - 4);
                float acc = 0.0f;
                #pragma unroll
                for (int a = 0; a < 4; a++) {
                    int rr = p + 1 - a;
                    if (rr < 0 || rr >= HH) continue;
                    #pragma unroll
                    for (int b = 0; b < 4; b++) {
                        int cc = q + 1 - b;
                        if (cc < 0 || cc >= WW) continue;
                        acc = fmaf(kk[a * 4 + b], xin[rr * WW + cc], acc);
                    }
                }
                yo[p * WW + q] = acc;
            }
        }
    }
}

extern "C" void kernel_launch(void* const* d_in, const int* in_sizes, int n_in,
                              void* d_out, int out_size) {
    const float* x    = (const float*)d_in[0];
    const float* kern = (const float*)d_in[1];
    float* out = (float*)d_out;

    int n = in_sizes[0];
    int nimg = n / (HH * WW);   // B*C images of 256x256

    Blur_455266533538_kernel<<<nimg * 4, 256>>>(x, kern, out, nimg);
}